// round 15
// baseline (speedup 1.0000x reference)
#include <cuda_runtime.h>
#include <cuda_bf16.h>
#include <math.h>
#include <stdint.h>

#define BATCH 2
#define SEQ   2048
#define DIM   512
#define NH    8
#define BHN   16
#define SD    (SEQ*DIM)
#define SS    (SEQ*SEQ)
#define SCALE 0.04419417382415922f
#define RFREQ (-0.025952563241307517f)   // -log2(10000)/512

typedef __nv_bfloat16 bf16;

// ---------------- scratch (device globals; no runtime alloc) ----------------
__device__ bf16  g_qs_hi[2097152],  g_qs_lo[2097152];    // q split [m][k]
__device__ bf16  g_w_hi[6291456],   g_w_lo[6291456];     // W split natural [w*8+h][z][d]
__device__ bf16  g_wo_hi[2097152],  g_wo_lo[2097152];    // Wo split natural [k][n]
__device__ bf16  g_qk_hi[33554432], g_qk_lo[33554432];   // qh(0)/kh(+16M) [bh][s][d]
__device__ bf16  g_v_hi[16777216],  g_v_lo[16777216];    // V split natural [bh][s][d]
__device__ bf16  g_p_hi[67108864],  g_p_lo[67108864];    // P split natural [bh][z][s]
__device__ bf16  g_at_hi[16777216], g_at_lo[16777216];   // attn split [bh][s][d]
__device__ float g_scores[67108864];                     // fp32 scores
__device__ float g_part[8388608];                        // oproj split-K partials [4][m][n]

__device__ __forceinline__ void cp16(void* sdst, const void* gsrc) {
    uint32_t sa = (uint32_t)__cvta_generic_to_shared(sdst);
    asm volatile("cp.async.cg.shared.global [%0], [%1], 16;" :: "r"(sa), "l"(gsrc));
}
__device__ __forceinline__ void cp_commit() { asm volatile("cp.async.commit_group;"); }
template<int N> __device__ __forceinline__ void cp_wait() {
    asm volatile("cp.async.wait_group %0;" :: "n"(N));
}
__device__ __forceinline__ void mma16(float* c, const uint32_t* a, const uint32_t* b) {
    asm volatile("mma.sync.aligned.m16n8k16.row.col.f32.bf16.bf16.f32 "
        "{%0,%1,%2,%3}, {%4,%5,%6,%7}, {%8,%9}, {%0,%1,%2,%3};"
        : "+f"(c[0]), "+f"(c[1]), "+f"(c[2]), "+f"(c[3])
        : "r"(a[0]), "r"(a[1]), "r"(a[2]), "r"(a[3]), "r"(b[0]), "r"(b[1]));
}
#define LDSMX4(r0,r1,r2,r3,addr) \
    asm volatile("ldmatrix.sync.aligned.m8n8.x4.shared.b16 {%0,%1,%2,%3}, [%4];" \
        : "=r"(r0), "=r"(r1), "=r"(r2), "=r"(r3) : "r"(addr))
#define LDSMX4T(r0,r1,r2,r3,addr) \
    asm volatile("ldmatrix.sync.aligned.m8n8.x4.trans.shared.b16 {%0,%1,%2,%3}, [%4];" \
        : "=r"(r0), "=r"(r1), "=r"(r2), "=r"(r3) : "r"(addr))

// pack {x0 -> low, x1 -> high} as bf16x2 hi + bf16x2 residual lo
__device__ __forceinline__ void split2(float x0, float x1, uint32_t& hi, uint32_t& lo) {
    uint32_t h;
    asm("cvt.rn.bf16x2.f32 %0, %1, %2;" : "=r"(h) : "f"(x1), "f"(x0));
    hi = h;
    float h0 = __uint_as_float(h << 16);
    float h1 = __uint_as_float(h & 0xFFFF0000u);
    asm("cvt.rn.bf16x2.f32 %0, %1, %2;" : "=r"(lo) : "f"(x1 - h1), "f"(x0 - h0));
}

#define PK 40       // K-major stage pitch (bf16): [128 rows][32 k + 8 pad]
#define PM 136      // MN-major stage pitch (bf16): [32 k][128 mn + 8 pad]
#define ARRB 10240  // bytes per operand array (128*40*2 >= 32*136*2)
#define SMEMB (2*4*ARRB)   // 81920

// ---------------------------------------------------------------------------
// Unified pre-split bf16 GEMM with ldmatrix fragments, K=32 stages,
// single-sync pipeline.  128x128 CTA tile, 8 warps of 64x32, 2 CTA/SM.
// KIND: 0=proj(+RoPE), 1=scores, 2=PV, 3=oproj(split-K 4).
// ---------------------------------------------------------------------------
template<int KIND>
__global__ __launch_bounds__(256, 2) void mma_kernel(float* __restrict__ cout)
{
    constexpr int AOR = (KIND == 2) ? 1 : 0;
    constexpr int BOR = (KIND == 1) ? 0 : 1;

    int m0, n0, kstart, kend;
    const bf16 *Ah = nullptr, *Al = nullptr, *Bh = nullptr, *Bl = nullptr;
    size_t lda = 0, ldb = 0;
    int h = 0, which = 0, bh = 0;

    if constexpr (KIND == 0) {
        which = blockIdx.z >> 3; h = blockIdx.z & 7;
        m0 = blockIdx.y * 128; n0 = blockIdx.x * 128; kstart = 0; kend = 512;
        Ah = g_qs_hi; Al = g_qs_lo; lda = 512;
        Bh = g_w_hi + (size_t)blockIdx.z * 262144;
        Bl = g_w_lo + (size_t)blockIdx.z * 262144; ldb = 512;
    } else if constexpr (KIND == 1) {
        if (blockIdx.x > blockIdx.y) return;
        bh = blockIdx.z;
        m0 = blockIdx.y * 128; n0 = blockIdx.x * 128; kstart = 0; kend = 512;
        Ah = g_qk_hi + (size_t)bh * SD;            Al = g_qk_lo + (size_t)bh * SD; lda = 512;
        Bh = g_qk_hi + 16777216 + (size_t)bh * SD; Bl = g_qk_lo + 16777216 + (size_t)bh * SD; ldb = 512;
    } else if constexpr (KIND == 2) {
        bh = blockIdx.z;
        m0 = blockIdx.y * 128; n0 = blockIdx.x * 128; kstart = m0; kend = SEQ;
        Ah = g_p_hi + (size_t)bh * SS; Al = g_p_lo + (size_t)bh * SS; lda = SEQ;  // [z][s]
        Bh = g_v_hi + (size_t)bh * SD; Bl = g_v_lo + (size_t)bh * SD; ldb = 512;  // [z][d]
    } else {
        m0 = blockIdx.y * 128; n0 = blockIdx.x * 128;
        kstart = blockIdx.z * 1024; kend = kstart + 1024;
        Ah = g_at_hi; Al = g_at_lo; lda = 512;   // gather handles layout
        Bh = g_wo_hi; Bl = g_wo_lo; ldb = 512;   // [k][n]
        cout = g_part + (size_t)blockIdx.z * 2097152;
    }

    extern __shared__ char smc[];
    const uint32_t sbase = (uint32_t)__cvta_generic_to_shared(smc);

    const int tid = threadIdx.x;
    const int wid = tid >> 5, lane = tid & 31;
    const int mw = (wid >> 2) * 64, nw = (wid & 3) * 32;
    const int g = lane >> 2, t = lane & 3;

    float acc[4][4][4];
#pragma unroll
    for (int a = 0; a < 4; a++)
#pragma unroll
        for (int b = 0; b < 4; b++)
#pragma unroll
            for (int c = 0; c < 4; c++) acc[a][b][c] = 0.f;

    // ldmatrix per-lane byte offsets (stage-invariant); chunk strides:
    constexpr int ACH = AOR ? 16 * PM * 2 : 32;
    constexpr int BCH = BOR ? 16 * PM * 2 : 32;
    int aoff[4], boff[2];
#pragma unroll
    for (int mt = 0; mt < 4; mt++) {
        if constexpr (AOR == 0)
            aoff[mt] = ((mw + mt * 16 + (lane & 15)) * PK + ((lane >> 4) << 3)) * 2;
        else
            aoff[mt] = (((lane & 7) + ((lane >> 4) << 3)) * PM + mw + mt * 16 + (((lane >> 3) & 1) << 3)) * 2;
    }
#pragma unroll
    for (int p = 0; p < 2; p++) {
        if constexpr (BOR == 0)
            boff[p] = ((nw + (2 * p + (lane >> 4)) * 8 + (lane & 7)) * PK + (((lane >> 3) & 1) << 3)) * 2;
        else
            boff[p] = (((lane & 7) + (((lane >> 3) & 1) << 3)) * PM + nw + (2 * p + (lane >> 4)) * 8) * 2;
    }

    const int nStages = (kend - kstart) >> 5;

    auto load_stage = [&](int s, int buf) {
        char* base = smc + buf * (4 * ARRB);
        const int k0 = kstart + (s << 5);
        // ---- A ----
#pragma unroll
        for (int j = 0; j < 2; j++) {
            const int ci = tid + (j << 8);
            if constexpr (AOR == 0) {
                const int row = ci >> 2, c8 = (ci & 3) * 8;
                size_t aoffg;
                if constexpr (KIND == 3) {
                    const int m = m0 + row, k = k0 + c8;
                    aoffg = (((size_t)((m >> 11) * 8 + (k >> 9))) * SEQ + (m & (SEQ - 1))) * 512 + (k & 511);
                } else {
                    aoffg = (size_t)(m0 + row) * lda + k0 + c8;
                }
                const int so = (row * PK + c8) * 2;
                cp16(base + so, Ah + aoffg);
                cp16(base + ARRB + so, Al + aoffg);
            } else {
                const int row = ci >> 4, c8 = (ci & 15) * 8;
                const size_t aoffg = (size_t)(k0 + row) * lda + m0 + c8;
                const int so = (row * PM + c8) * 2;
                cp16(base + so, Ah + aoffg);
                cp16(base + ARRB + so, Al + aoffg);
            }
        }
        // ---- B ----
#pragma unroll
        for (int j = 0; j < 2; j++) {
            const int ci = tid + (j << 8);
            if constexpr (BOR == 0) {
                const int row = ci >> 2, c8 = (ci & 3) * 8;
                const size_t boffg = (size_t)(n0 + row) * ldb + k0 + c8;
                const int so = (row * PK + c8) * 2;
                cp16(base + 2 * ARRB + so, Bh + boffg);
                cp16(base + 3 * ARRB + so, Bl + boffg);
            } else {
                const int row = ci >> 4, c8 = (ci & 15) * 8;
                const size_t boffg = (size_t)(k0 + row) * ldb + n0 + c8;
                const int so = (row * PM + c8) * 2;
                cp16(base + 2 * ARRB + so, Bh + boffg);
                cp16(base + 3 * ARRB + so, Bl + boffg);
            }
        }
        cp_commit();
    };

    load_stage(0, 0);

    for (int s = 0; s < nStages; s++) {
        const int buf = s & 1;
        cp_wait<0>();
        __syncthreads();
        if (s + 1 < nStages) load_stage(s + 1, buf ^ 1);

        const uint32_t sAh = sbase + buf * (4 * ARRB);
        const uint32_t sAl = sAh + ARRB;
        const uint32_t sBh = sAh + 2 * ARRB;
        const uint32_t sBl = sAh + 3 * ARRB;

#pragma unroll
        for (int c = 0; c < 2; c++) {
            uint32_t bhf[4][2], blf[4][2];
#pragma unroll
            for (int p = 0; p < 2; p++) {
                if constexpr (BOR == 0) {
                    LDSMX4(bhf[2*p][0], bhf[2*p][1], bhf[2*p+1][0], bhf[2*p+1][1], sBh + boff[p] + c * BCH);
                    LDSMX4(blf[2*p][0], blf[2*p][1], blf[2*p+1][0], blf[2*p+1][1], sBl + boff[p] + c * BCH);
                } else {
                    LDSMX4T(bhf[2*p][0], bhf[2*p][1], bhf[2*p+1][0], bhf[2*p+1][1], sBh + boff[p] + c * BCH);
                    LDSMX4T(blf[2*p][0], blf[2*p][1], blf[2*p+1][0], blf[2*p+1][1], sBl + boff[p] + c * BCH);
                }
            }
#pragma unroll
            for (int mt = 0; mt < 4; mt++) {
                uint32_t ah[4], al[4];
                if constexpr (AOR == 0) {
                    LDSMX4(ah[0], ah[1], ah[2], ah[3], sAh + aoff[mt] + c * ACH);
                    LDSMX4(al[0], al[1], al[2], al[3], sAl + aoff[mt] + c * ACH);
                } else {
                    LDSMX4T(ah[0], ah[1], ah[2], ah[3], sAh + aoff[mt] + c * ACH);
                    LDSMX4T(al[0], al[1], al[2], al[3], sAl + aoff[mt] + c * ACH);
                }
#pragma unroll
                for (int nt = 0; nt < 4; nt++) {
                    mma16(acc[mt][nt], al, bhf[nt]);
                    mma16(acc[mt][nt], ah, blf[nt]);
                    mma16(acc[mt][nt], ah, bhf[nt]);
                }
            }
        }
    }

    // -------- epilogue: c0,c1 -> (row g, col 2t,2t+1); c2,c3 -> row g+8 -----
#pragma unroll
    for (int mt = 0; mt < 4; mt++) {
#pragma unroll
        for (int nt = 0; nt < 4; nt++) {
            float* cc = acc[mt][nt];
            const int gr = m0 + mw + mt * 16 + g;
            const int gc = n0 + nw + nt * 8 + t * 2;
#pragma unroll
            for (int half = 0; half < 2; half++) {
                const int r = gr + half * 8;
                float v0 = cc[half * 2], v1 = cc[half * 2 + 1];
                if constexpr (KIND == 0) {
                    const int bb = r >> 11, ss = r & (SEQ - 1);
                    const size_t idx = (((size_t)(bb * 8 + h)) * SEQ + ss) * 512 + gc;
                    uint32_t hw, lw;
                    if (which < 2) {
                        float inv = exp2f((float)gc * RFREQ);
                        float ang = (float)ss * inv, sn, cs;
                        sincosf(ang, &sn, &cs);
                        float x1 = v0, x2 = v1;
                        v0 = x1 * cs - x2 * sn;
                        v1 = x1 * sn + x2 * cs;
                        split2(v0, v1, hw, lw);
                        const size_t o = (size_t)which * 16777216 + idx;
                        *(uint32_t*)(g_qk_hi + o) = hw;
                        *(uint32_t*)(g_qk_lo + o) = lw;
                    } else {
                        split2(v0, v1, hw, lw);
                        *(uint32_t*)(g_v_hi + idx) = hw;
                        *(uint32_t*)(g_v_lo + idx) = lw;
                    }
                } else if constexpr (KIND == 1) {
                    *(float2*)(g_scores + (size_t)bh * SS + (size_t)r * SEQ + gc) =
                        make_float2(v0 * SCALE, v1 * SCALE);
                } else if constexpr (KIND == 2) {
                    uint32_t hw, lw;
                    split2(v0, v1, hw, lw);
                    const size_t o = (size_t)bh * SD + (size_t)r * 512 + gc;
                    *(uint32_t*)(g_at_hi + o) = hw;
                    *(uint32_t*)(g_at_lo + o) = lw;
                } else {
                    *(float2*)(cout + (size_t)r * 512 + gc) = make_float2(v0, v1);
                }
            }
        }
    }
}

// ---------------------------------------------------------------------------
// oproj split-K reduction: out = sum of 4 partials (deterministic order)
// ---------------------------------------------------------------------------
__global__ __launch_bounds__(256) void reduce_out_kernel(float* __restrict__ out)
{
    const int idx = blockIdx.x * 256 + threadIdx.x;
    float4 a = *(const float4*)(g_part + (size_t)idx * 4);
    float4 b = *(const float4*)(g_part + 2097152 + (size_t)idx * 4);
    float4 c = *(const float4*)(g_part + 4194304 + (size_t)idx * 4);
    float4 d = *(const float4*)(g_part + 6291456 + (size_t)idx * 4);
    float4 o = make_float4(((a.x + b.x) + c.x) + d.x,
                           ((a.y + b.y) + c.y) + d.y,
                           ((a.z + b.z) + c.z) + d.z,
                           ((a.w + b.w) + c.w) + d.w);
    *(float4*)(out + (size_t)idx * 4) = o;
}

// ---------------------------------------------------------------------------
// Elementwise split kernels (no transposes anywhere).
// ---------------------------------------------------------------------------
__global__ __launch_bounds__(256) void split_q_kernel(const float* __restrict__ q)
{
    const int idx = blockIdx.x * 256 + threadIdx.x;
    float4 v = *(const float4*)(q + (size_t)idx * 4);
    uint32_t h0, l0, h1, l1;
    split2(v.x, v.y, h0, l0);
    split2(v.z, v.w, h1, l1);
    uint32_t* oh = (uint32_t*)g_qs_hi + (size_t)idx * 2;
    uint32_t* ol = (uint32_t*)g_qs_lo + (size_t)idx * 2;
    oh[0] = h0; oh[1] = h1;
    ol[0] = l0; ol[1] = l1;
}
__global__ __launch_bounds__(256) void split_w_kernel(const float* __restrict__ a,
                                                      const float* __restrict__ b,
                                                      const float* __restrict__ c)
{
    const int bz = blockIdx.z;
    const int which = bz >> 3, hh = bz & 7;
    const float* src = (which == 0 ? a : (which == 1 ? b : c)) + (size_t)hh * 262144;
    const int idx = blockIdx.x * 256 + threadIdx.x;
    float4 v = *(const float4*)(src + (size_t)idx * 4);
    uint32_t h0, l0, h1, l1;
    split2(v.x, v.y, h0, l0);
    split2(v.z, v.w, h1, l1);
    uint32_t* oh = (uint32_t*)(g_w_hi + (size_t)bz * 262144) + (size_t)idx * 2;
    uint32_t* ol = (uint32_t*)(g_w_lo + (size_t)bz * 262144) + (size_t)idx * 2;
    oh[0] = h0; oh[1] = h1;
    ol[0] = l0; ol[1] = l1;
}
__global__ __launch_bounds__(256) void split_wo_kernel(const float* __restrict__ w)
{
    const int idx = blockIdx.x * 256 + threadIdx.x;
    float4 v = *(const float4*)(w + (size_t)idx * 4);
    uint32_t h0, l0, h1, l1;
    split2(v.x, v.y, h0, l0);
    split2(v.z, v.w, h1, l1);
    uint32_t* oh = (uint32_t*)g_wo_hi + (size_t)idx * 2;
    uint32_t* ol = (uint32_t*)g_wo_lo + (size_t)idx * 2;
    oh[0] = h0; oh[1] = h1;
    ol[0] = l0; ol[1] = l1;
}

// ---------------------------------------------------------------------------
// Causal row softmax: fp32 scores -> bf16 hi/lo probs (zeros for k > q).
// ---------------------------------------------------------------------------
__global__ __launch_bounds__(256) void softmax_kernel()
{
    const int row = blockIdx.x;
    const int qpos = row & (SEQ - 1);
    const float* p = g_scores + (size_t)row * SEQ;
    bf16* oh = g_p_hi + (size_t)row * SEQ;
    bf16* ol = g_p_lo + (size_t)row * SEQ;
    const int n = qpos + 1;
    const int t = threadIdx.x;
    __shared__ float red[8];

    float vals[8];
    int cnt = 0;
    float m = -INFINITY;
    for (int i = t; i < n; i += 256) { float v = p[i]; vals[cnt++] = v; m = fmaxf(m, v); }
#pragma unroll
    for (int off = 16; off; off >>= 1) m = fmaxf(m, __shfl_xor_sync(0xffffffffu, m, off));
    if ((t & 31) == 0) red[t >> 5] = m;
    __syncthreads();
    if (t == 0) { float mm = red[0];
#pragma unroll
        for (int w = 1; w < 8; w++) mm = fmaxf(mm, red[w]); red[0] = mm; }
    __syncthreads();
    m = red[0];
    __syncthreads();

    float l = 0.f;
#pragma unroll
    for (int c = 0; c < 8; c++) if (c < cnt) { vals[c] = expf(vals[c] - m); l += vals[c]; }
#pragma unroll
    for (int off = 16; off; off >>= 1) l += __shfl_xor_sync(0xffffffffu, l, off);
    if ((t & 31) == 0) red[t >> 5] = l;
    __syncthreads();
    if (t == 0) { float ss = 0.f;
#pragma unroll
        for (int w = 0; w < 8; w++) ss += red[w]; red[0] = ss; }
    __syncthreads();
    const float inv = 1.0f / red[0];

    int c = 0;
    for (int i = t; i < SEQ; i += 256) {
        float o = 0.f;
        if (i < n) o = vals[c++] * inv;
        bf16 hv = __float2bfloat16(o);
        bf16 lv = __float2bfloat16(o - __bfloat162float(hv));
        oh[i] = hv;
        ol[i] = lv;
    }
}

// ---------------------------------------------------------------------------
extern "C" void kernel_launch(void* const* d_in, const int* in_sizes, int n_in,
                              void* d_out, int out_size)
{
    const float* q  = (const float*)d_in[0];
    const float* Wq = (const float*)d_in[1];
    const float* Wk = (const float*)d_in[2];
    const float* Wv = (const float*)d_in[3];
    const float* Wo = (const float*)d_in[4];
    float* out = (float*)d_out;

    static int attr_done = 0;
    if (!attr_done) {
        cudaFuncSetAttribute(mma_kernel<0>, cudaFuncAttributeMaxDynamicSharedMemorySize, SMEMB);
        cudaFuncSetAttribute(mma_kernel<1>, cudaFuncAttributeMaxDynamicSharedMemorySize, SMEMB);
        cudaFuncSetAttribute(mma_kernel<2>, cudaFuncAttributeMaxDynamicSharedMemorySize, SMEMB);
        cudaFuncSetAttribute(mma_kernel<3>, cudaFuncAttributeMaxDynamicSharedMemorySize, SMEMB);
        attr_done = 1;
    }

    split_q_kernel<<<2048, 256>>>(q);
    split_w_kernel<<<dim3(256, 1, 24), 256>>>(Wq, Wk, Wv);
    split_wo_kernel<<<2048, 256>>>(Wo);

    mma_kernel<0><<<dim3(4, 32, 24), 256, SMEMB>>>(nullptr);   // QKV proj + RoPE / V split
    mma_kernel<1><<<dim3(16, 16, 16), 256, SMEMB>>>(nullptr);  // scores (causal tiles)
    softmax_kernel<<<BHN * SEQ, 256>>>();                      // probs -> bf16 hi/lo
    mma_kernel<2><<<dim3(4, 16, 16), 256, SMEMB>>>(nullptr);   // O = P^T V
    mma_kernel<3><<<dim3(4, 32, 4), 256, SMEMB>>>(nullptr);    // out proj (split-K 4)
    reduce_out_kernel<<<2048, 256>>>(out);                     // sum partials
}

// round 16
// speedup vs baseline: 1.5417x; 1.5417x over previous
#include <cuda_runtime.h>
#include <cuda_bf16.h>
#include <math.h>
#include <stdint.h>

#define BATCH 2
#define SEQ   2048
#define DIM   512
#define NH    8
#define BHN   16
#define SD    (SEQ*DIM)
#define SS    (SEQ*SEQ)
#define SCALE 0.04419417382415922f
#define RFREQ (-0.025952563241307517f)   // -log2(10000)/512

typedef __nv_bfloat16 bf16;

// ---------------- scratch (device globals; no runtime alloc) ----------------
__device__ bf16  g_qs_hi[2097152],  g_qs_lo[2097152];    // q split [m][k]
__device__ bf16  g_w_hi[6291456],   g_w_lo[6291456];     // W split natural [w*8+h][z][d]
__device__ bf16  g_wo_hi[2097152],  g_wo_lo[2097152];    // Wo split natural [k][n]
__device__ bf16  g_qk_hi[33554432], g_qk_lo[33554432];   // qh(0)/kh(+16M) [bh][s][d]
__device__ bf16  g_v_hi[16777216],  g_v_lo[16777216];    // V split natural [bh][s][d]
__device__ bf16  g_p_hi[67108864],  g_p_lo[67108864];    // P split natural [bh][z][s]
__device__ bf16  g_at_hi[16777216], g_at_lo[16777216];   // attn split [bh][s][d]
__device__ float g_scores[67108864];                     // fp32 scores
__device__ float g_part[8388608];                        // oproj split-K partials [4][m][n]

__device__ __forceinline__ void cp16(void* sdst, const void* gsrc) {
    uint32_t sa = (uint32_t)__cvta_generic_to_shared(sdst);
    asm volatile("cp.async.cg.shared.global [%0], [%1], 16;" :: "r"(sa), "l"(gsrc));
}
__device__ __forceinline__ void cp_commit() { asm volatile("cp.async.commit_group;"); }
template<int N> __device__ __forceinline__ void cp_wait() {
    asm volatile("cp.async.wait_group %0;" :: "n"(N));
}
__device__ __forceinline__ void mma16(float* c, const uint32_t* a, const uint32_t* b) {
    asm volatile("mma.sync.aligned.m16n8k16.row.col.f32.bf16.bf16.f32 "
        "{%0,%1,%2,%3}, {%4,%5,%6,%7}, {%8,%9}, {%0,%1,%2,%3};"
        : "+f"(c[0]), "+f"(c[1]), "+f"(c[2]), "+f"(c[3])
        : "r"(a[0]), "r"(a[1]), "r"(a[2]), "r"(a[3]), "r"(b[0]), "r"(b[1]));
}
#define LDSMX4(r0,r1,r2,r3,addr) \
    asm volatile("ldmatrix.sync.aligned.m8n8.x4.shared.b16 {%0,%1,%2,%3}, [%4];" \
        : "=r"(r0), "=r"(r1), "=r"(r2), "=r"(r3) : "r"(addr))
#define LDSMX4T(r0,r1,r2,r3,addr) \
    asm volatile("ldmatrix.sync.aligned.m8n8.x4.trans.shared.b16 {%0,%1,%2,%3}, [%4];" \
        : "=r"(r0), "=r"(r1), "=r"(r2), "=r"(r3) : "r"(addr))

// pack {x0 -> low, x1 -> high} as bf16x2 hi + bf16x2 residual lo
__device__ __forceinline__ void split2(float x0, float x1, uint32_t& hi, uint32_t& lo) {
    uint32_t h;
    asm("cvt.rn.bf16x2.f32 %0, %1, %2;" : "=r"(h) : "f"(x1), "f"(x0));
    hi = h;
    float h0 = __uint_as_float(h << 16);
    float h1 = __uint_as_float(h & 0xFFFF0000u);
    asm("cvt.rn.bf16x2.f32 %0, %1, %2;" : "=r"(lo) : "f"(x1 - h1), "f"(x0 - h0));
}

#define PK 40       // K-major stage pitch (bf16): [128 rows][32 k + 8 pad]
#define PM 136      // MN-major stage pitch (bf16): [32 k][128 mn + 8 pad]
#define ARRB 10240  // bytes per operand array (128*40*2 >= 32*136*2)
#define SMEMB (2*4*ARRB)   // 81920

// ---------------------------------------------------------------------------
// Unified pre-split bf16 GEMM with ldmatrix fragments, K=32 stages,
// single-sync pipeline.  128x128 CTA tile, 8 warps of 64x32, 2 CTA/SM.
// KIND: 0=proj(+RoPE), 1=scores, 2=PV, 3=oproj(split-K 4).
// ---------------------------------------------------------------------------
template<int KIND>
__global__ __launch_bounds__(256, 2) void mma_kernel(float* __restrict__ cout)
{
    constexpr int AOR = (KIND == 2) ? 1 : 0;
    constexpr int BOR = (KIND == 1) ? 0 : 1;

    int m0, n0, kstart, kend;
    const bf16 *Ah = nullptr, *Al = nullptr, *Bh = nullptr, *Bl = nullptr;
    size_t lda = 0, ldb = 0;
    int h = 0, which = 0, bh = 0;

    if constexpr (KIND == 0) {
        which = blockIdx.z >> 3; h = blockIdx.z & 7;
        m0 = blockIdx.y * 128; n0 = blockIdx.x * 128; kstart = 0; kend = 512;
        Ah = g_qs_hi; Al = g_qs_lo; lda = 512;
        Bh = g_w_hi + (size_t)blockIdx.z * 262144;
        Bl = g_w_lo + (size_t)blockIdx.z * 262144; ldb = 512;
    } else if constexpr (KIND == 1) {
        if (blockIdx.x > blockIdx.y) return;
        bh = blockIdx.z;
        m0 = blockIdx.y * 128; n0 = blockIdx.x * 128; kstart = 0; kend = 512;
        Ah = g_qk_hi + (size_t)bh * SD;            Al = g_qk_lo + (size_t)bh * SD; lda = 512;
        Bh = g_qk_hi + 16777216 + (size_t)bh * SD; Bl = g_qk_lo + 16777216 + (size_t)bh * SD; ldb = 512;
    } else if constexpr (KIND == 2) {
        bh = blockIdx.z;
        m0 = blockIdx.y * 128; n0 = blockIdx.x * 128; kstart = m0; kend = SEQ;
        Ah = g_p_hi + (size_t)bh * SS; Al = g_p_lo + (size_t)bh * SS; lda = SEQ;  // [z][s]
        Bh = g_v_hi + (size_t)bh * SD; Bl = g_v_lo + (size_t)bh * SD; ldb = 512;  // [z][d]
    } else {
        m0 = blockIdx.y * 128; n0 = blockIdx.x * 128;
        kstart = blockIdx.z * 1024; kend = kstart + 1024;
        Ah = g_at_hi; Al = g_at_lo; lda = 512;   // gather handles layout
        Bh = g_wo_hi; Bl = g_wo_lo; ldb = 512;   // [k][n]
        cout = g_part + (size_t)blockIdx.z * 2097152;
    }

    extern __shared__ char smc[];
    const uint32_t sbase = (uint32_t)__cvta_generic_to_shared(smc);

    const int tid = threadIdx.x;
    const int wid = tid >> 5, lane = tid & 31;
    const int mw = (wid >> 2) * 64, nw = (wid & 3) * 32;
    const int g = lane >> 2, t = lane & 3;

    float acc[4][4][4];
#pragma unroll
    for (int a = 0; a < 4; a++)
#pragma unroll
        for (int b = 0; b < 4; b++)
#pragma unroll
            for (int c = 0; c < 4; c++) acc[a][b][c] = 0.f;

    // ldmatrix per-lane byte offsets (stage-invariant); chunk strides:
    constexpr int ACH = AOR ? 16 * PM * 2 : 32;
    constexpr int BCH = BOR ? 16 * PM * 2 : 32;
    int aoff[4], boff[2];
#pragma unroll
    for (int mt = 0; mt < 4; mt++) {
        if constexpr (AOR == 0)
            aoff[mt] = ((mw + mt * 16 + (lane & 15)) * PK + ((lane >> 4) << 3)) * 2;
        else
            aoff[mt] = (((lane & 7) + ((lane >> 4) << 3)) * PM + mw + mt * 16 + (((lane >> 3) & 1) << 3)) * 2;
    }
#pragma unroll
    for (int p = 0; p < 2; p++) {
        if constexpr (BOR == 0)
            boff[p] = ((nw + (2 * p + (lane >> 4)) * 8 + (lane & 7)) * PK + (((lane >> 3) & 1) << 3)) * 2;
        else
            boff[p] = (((lane & 7) + (((lane >> 3) & 1) << 3)) * PM + nw + (2 * p + (lane >> 4)) * 8) * 2;
    }

    const int nStages = (kend - kstart) >> 5;

    auto load_stage = [&](int s, int buf) {
        char* base = smc + buf * (4 * ARRB);
        const int k0 = kstart + (s << 5);
        // ---- A ----
#pragma unroll
        for (int j = 0; j < 2; j++) {
            const int ci = tid + (j << 8);
            if constexpr (AOR == 0) {
                const int row = ci >> 2, c8 = (ci & 3) * 8;
                size_t aoffg;
                if constexpr (KIND == 3) {
                    const int m = m0 + row, k = k0 + c8;
                    aoffg = (((size_t)((m >> 11) * 8 + (k >> 9))) * SEQ + (m & (SEQ - 1))) * 512 + (k & 511);
                } else {
                    aoffg = (size_t)(m0 + row) * lda + k0 + c8;
                }
                const int so = (row * PK + c8) * 2;
                cp16(base + so, Ah + aoffg);
                cp16(base + ARRB + so, Al + aoffg);
            } else {
                const int row = ci >> 4, c8 = (ci & 15) * 8;
                const size_t aoffg = (size_t)(k0 + row) * lda + m0 + c8;
                const int so = (row * PM + c8) * 2;
                cp16(base + so, Ah + aoffg);
                cp16(base + ARRB + so, Al + aoffg);
            }
        }
        // ---- B ----
#pragma unroll
        for (int j = 0; j < 2; j++) {
            const int ci = tid + (j << 8);
            if constexpr (BOR == 0) {
                const int row = ci >> 2, c8 = (ci & 3) * 8;
                const size_t boffg = (size_t)(n0 + row) * ldb + k0 + c8;
                const int so = (row * PK + c8) * 2;
                cp16(base + 2 * ARRB + so, Bh + boffg);
                cp16(base + 3 * ARRB + so, Bl + boffg);
            } else {
                const int row = ci >> 4, c8 = (ci & 15) * 8;
                const size_t boffg = (size_t)(k0 + row) * ldb + n0 + c8;
                const int so = (row * PM + c8) * 2;
                cp16(base + 2 * ARRB + so, Bh + boffg);
                cp16(base + 3 * ARRB + so, Bl + boffg);
            }
        }
        cp_commit();
    };

    load_stage(0, 0);

    for (int s = 0; s < nStages; s++) {
        const int buf = s & 1;
        cp_wait<0>();
        __syncthreads();
        if (s + 1 < nStages) load_stage(s + 1, buf ^ 1);

        const uint32_t sAh = sbase + buf * (4 * ARRB);
        const uint32_t sAl = sAh + ARRB;
        const uint32_t sBh = sAh + 2 * ARRB;
        const uint32_t sBl = sAh + 3 * ARRB;

#pragma unroll
        for (int c = 0; c < 2; c++) {
            uint32_t bhf[4][2], blf[4][2];
#pragma unroll
            for (int p = 0; p < 2; p++) {
                if constexpr (BOR == 0) {
                    LDSMX4(bhf[2*p][0], bhf[2*p][1], bhf[2*p+1][0], bhf[2*p+1][1], sBh + boff[p] + c * BCH);
                    LDSMX4(blf[2*p][0], blf[2*p][1], blf[2*p+1][0], blf[2*p+1][1], sBl + boff[p] + c * BCH);
                } else {
                    LDSMX4T(bhf[2*p][0], bhf[2*p][1], bhf[2*p+1][0], bhf[2*p+1][1], sBh + boff[p] + c * BCH);
                    LDSMX4T(blf[2*p][0], blf[2*p][1], blf[2*p+1][0], blf[2*p+1][1], sBl + boff[p] + c * BCH);
                }
            }
#pragma unroll
            for (int mt = 0; mt < 4; mt++) {
                uint32_t ah[4], al[4];
                if constexpr (AOR == 0) {
                    LDSMX4(ah[0], ah[1], ah[2], ah[3], sAh + aoff[mt] + c * ACH);
                    LDSMX4(al[0], al[1], al[2], al[3], sAl + aoff[mt] + c * ACH);
                } else {
                    LDSMX4T(ah[0], ah[1], ah[2], ah[3], sAh + aoff[mt] + c * ACH);
                    LDSMX4T(al[0], al[1], al[2], al[3], sAl + aoff[mt] + c * ACH);
                }
#pragma unroll
                for (int nt = 0; nt < 4; nt++) {
                    mma16(acc[mt][nt], al, bhf[nt]);
                    mma16(acc[mt][nt], ah, blf[nt]);
                    mma16(acc[mt][nt], ah, bhf[nt]);
                }
            }
        }
    }

    // -------- epilogue: c0,c1 -> (row g, col 2t,2t+1); c2,c3 -> row g+8 -----
#pragma unroll
    for (int mt = 0; mt < 4; mt++) {
#pragma unroll
        for (int nt = 0; nt < 4; nt++) {
            float* cc = acc[mt][nt];
            const int gr = m0 + mw + mt * 16 + g;
            const int gc = n0 + nw + nt * 8 + t * 2;
#pragma unroll
            for (int half = 0; half < 2; half++) {
                const int r = gr + half * 8;
                float v0 = cc[half * 2], v1 = cc[half * 2 + 1];
                if constexpr (KIND == 0) {
                    const int bb = r >> 11, ss = r & (SEQ - 1);
                    const size_t idx = (((size_t)(bb * 8 + h)) * SEQ + ss) * 512 + gc;
                    uint32_t hw, lw;
                    if (which < 2) {
                        float inv = exp2f((float)gc * RFREQ);
                        float ang = (float)ss * inv, sn, cs;
                        sincosf(ang, &sn, &cs);
                        float x1 = v0, x2 = v1;
                        v0 = x1 * cs - x2 * sn;
                        v1 = x1 * sn + x2 * cs;
                        split2(v0, v1, hw, lw);
                        const size_t o = (size_t)which * 16777216 + idx;
                        *(uint32_t*)(g_qk_hi + o) = hw;
                        *(uint32_t*)(g_qk_lo + o) = lw;
                    } else {
                        split2(v0, v1, hw, lw);
                        *(uint32_t*)(g_v_hi + idx) = hw;
                        *(uint32_t*)(g_v_lo + idx) = lw;
                    }
                } else if constexpr (KIND == 1) {
                    *(float2*)(g_scores + (size_t)bh * SS + (size_t)r * SEQ + gc) =
                        make_float2(v0 * SCALE, v1 * SCALE);
                } else if constexpr (KIND == 2) {
                    uint32_t hw, lw;
                    split2(v0, v1, hw, lw);
                    const size_t o = (size_t)bh * SD + (size_t)r * 512 + gc;
                    *(uint32_t*)(g_at_hi + o) = hw;
                    *(uint32_t*)(g_at_lo + o) = lw;
                } else {
                    *(float2*)(cout + (size_t)r * 512 + gc) = make_float2(v0, v1);
                }
            }
        }
    }
}

// ---------------------------------------------------------------------------
// oproj split-K reduction: out = sum of 4 partials (deterministic order)
// ---------------------------------------------------------------------------
__global__ __launch_bounds__(256) void reduce_out_kernel(float* __restrict__ out)
{
    const int idx = blockIdx.x * 256 + threadIdx.x;
    float4 a = *(const float4*)(g_part + (size_t)idx * 4);
    float4 b = *(const float4*)(g_part + 2097152 + (size_t)idx * 4);
    float4 c = *(const float4*)(g_part + 4194304 + (size_t)idx * 4);
    float4 d = *(const float4*)(g_part + 6291456 + (size_t)idx * 4);
    float4 o = make_float4(((a.x + b.x) + c.x) + d.x,
                           ((a.y + b.y) + c.y) + d.y,
                           ((a.z + b.z) + c.z) + d.z,
                           ((a.w + b.w) + c.w) + d.w);
    *(float4*)(out + (size_t)idx * 4) = o;
}

// ---------------------------------------------------------------------------
// Elementwise split kernels (no transposes anywhere).
// ---------------------------------------------------------------------------
__global__ __launch_bounds__(256) void split_q_kernel(const float* __restrict__ q)
{
    const int idx = blockIdx.x * 256 + threadIdx.x;
    float4 v = *(const float4*)(q + (size_t)idx * 4);
    uint32_t h0, l0, h1, l1;
    split2(v.x, v.y, h0, l0);
    split2(v.z, v.w, h1, l1);
    uint32_t* oh = (uint32_t*)g_qs_hi + (size_t)idx * 2;
    uint32_t* ol = (uint32_t*)g_qs_lo + (size_t)idx * 2;
    oh[0] = h0; oh[1] = h1;
    ol[0] = l0; ol[1] = l1;
}
__global__ __launch_bounds__(256) void split_w_kernel(const float* __restrict__ a,
                                                      const float* __restrict__ b,
                                                      const float* __restrict__ c)
{
    const int bz = blockIdx.z;
    const int which = bz >> 3, hh = bz & 7;
    const float* src = (which == 0 ? a : (which == 1 ? b : c)) + (size_t)hh * 262144;
    const int idx = blockIdx.x * 256 + threadIdx.x;
    float4 v = *(const float4*)(src + (size_t)idx * 4);
    uint32_t h0, l0, h1, l1;
    split2(v.x, v.y, h0, l0);
    split2(v.z, v.w, h1, l1);
    uint32_t* oh = (uint32_t*)(g_w_hi + (size_t)bz * 262144) + (size_t)idx * 2;
    uint32_t* ol = (uint32_t*)(g_w_lo + (size_t)bz * 262144) + (size_t)idx * 2;
    oh[0] = h0; oh[1] = h1;
    ol[0] = l0; ol[1] = l1;
}
__global__ __launch_bounds__(256) void split_wo_kernel(const float* __restrict__ w)
{
    const int idx = blockIdx.x * 256 + threadIdx.x;
    float4 v = *(const float4*)(w + (size_t)idx * 4);
    uint32_t h0, l0, h1, l1;
    split2(v.x, v.y, h0, l0);
    split2(v.z, v.w, h1, l1);
    uint32_t* oh = (uint32_t*)g_wo_hi + (size_t)idx * 2;
    uint32_t* ol = (uint32_t*)g_wo_lo + (size_t)idx * 2;
    oh[0] = h0; oh[1] = h1;
    ol[0] = l0; ol[1] = l1;
}

// ---------------------------------------------------------------------------
// Causal row softmax: fp32 scores -> bf16 hi/lo probs (zeros for k > q).
// ---------------------------------------------------------------------------
__global__ __launch_bounds__(256) void softmax_kernel()
{
    const int row = blockIdx.x;
    const int qpos = row & (SEQ - 1);
    const float* p = g_scores + (size_t)row * SEQ;
    bf16* oh = g_p_hi + (size_t)row * SEQ;
    bf16* ol = g_p_lo + (size_t)row * SEQ;
    const int n = qpos + 1;
    const int t = threadIdx.x;
    __shared__ float red[8];

    float vals[8];
    int cnt = 0;
    float m = -INFINITY;
    for (int i = t; i < n; i += 256) { float v = p[i]; vals[cnt++] = v; m = fmaxf(m, v); }
#pragma unroll
    for (int off = 16; off; off >>= 1) m = fmaxf(m, __shfl_xor_sync(0xffffffffu, m, off));
    if ((t & 31) == 0) red[t >> 5] = m;
    __syncthreads();
    if (t == 0) { float mm = red[0];
#pragma unroll
        for (int w = 1; w < 8; w++) mm = fmaxf(mm, red[w]); red[0] = mm; }
    __syncthreads();
    m = red[0];
    __syncthreads();

    float l = 0.f;
#pragma unroll
    for (int c = 0; c < 8; c++) if (c < cnt) { vals[c] = expf(vals[c] - m); l += vals[c]; }
#pragma unroll
    for (int off = 16; off; off >>= 1) l += __shfl_xor_sync(0xffffffffu, l, off);
    if ((t & 31) == 0) red[t >> 5] = l;
    __syncthreads();
    if (t == 0) { float ss = 0.f;
#pragma unroll
        for (int w = 0; w < 8; w++) ss += red[w]; red[0] = ss; }
    __syncthreads();
    const float inv = 1.0f / red[0];

    int c = 0;
    for (int i = t; i < SEQ; i += 256) {
        float o = 0.f;
        if (i < n) o = vals[c++] * inv;
        bf16 hv = __float2bfloat16(o);
        bf16 lv = __float2bfloat16(o - __bfloat162float(hv));
        oh[i] = hv;
        ol[i] = lv;
    }
}

// ---------------------------------------------------------------------------
extern "C" void kernel_launch(void* const* d_in, const int* in_sizes, int n_in,
                              void* d_out, int out_size)
{
    const float* q  = (const float*)d_in[0];
    const float* Wq = (const float*)d_in[1];
    const float* Wk = (const float*)d_in[2];
    const float* Wv = (const float*)d_in[3];
    const float* Wo = (const float*)d_in[4];
    float* out = (float*)d_out;

    static int attr_done = 0;
    if (!attr_done) {
        cudaFuncSetAttribute(mma_kernel<0>, cudaFuncAttributeMaxDynamicSharedMemorySize, SMEMB);
        cudaFuncSetAttribute(mma_kernel<1>, cudaFuncAttributeMaxDynamicSharedMemorySize, SMEMB);
        cudaFuncSetAttribute(mma_kernel<2>, cudaFuncAttributeMaxDynamicSharedMemorySize, SMEMB);
        cudaFuncSetAttribute(mma_kernel<3>, cudaFuncAttributeMaxDynamicSharedMemorySize, SMEMB);
        attr_done = 1;
    }

    split_q_kernel<<<2048, 256>>>(q);
    split_w_kernel<<<dim3(256, 1, 24), 256>>>(Wq, Wk, Wv);
    split_wo_kernel<<<2048, 256>>>(Wo);

    mma_kernel<0><<<dim3(4, 32, 24), 256, SMEMB>>>(nullptr);   // QKV proj + RoPE / V split
    mma_kernel<1><<<dim3(16, 16, 16), 256, SMEMB>>>(nullptr);  // scores (causal tiles)
    softmax_kernel<<<BHN * SEQ, 256>>>();                      // probs -> bf16 hi/lo
    mma_kernel<2><<<dim3(4, 16, 16), 256, SMEMB>>>(nullptr);   // O = P^T V
    mma_kernel<3><<<dim3(4, 32, 4), 256, SMEMB>>>(nullptr);    // out proj (split-K 4)
    reduce_out_kernel<<<2048, 256>>>(out);                     // sum partials
}